// round 2
// baseline (speedup 1.0000x reference)
#include <cuda_runtime.h>

// TrajectoryGenerator fused kernel for GB300 (sm_103a).
// One warp == one scene (32 agents). Fully fused: embed -> enc LSTM(20) ->
// LN -> per-scene MHA -> LN -> MLP -> dec LSTM(30) -> output.
// All inner products use packed fma.rn.f32x2 (2 FMAs/lane/instr).

#define OBS   20
#define PRED  30
#define HDIM  32
#define EMBD  16
#define MLPD  64
#define NOISE 8
#define NHEAD 4
#define DHD   8
#define WARPS 8
#define TPB   256

typedef unsigned long long ull;

__device__ __forceinline__ ull ffma2(ull a, ull b, ull c) {
    ull d; asm("fma.rn.f32x2 %0, %1, %2, %3;" : "=l"(d) : "l"(a), "l"(b), "l"(c)); return d;
}
__device__ __forceinline__ ull fadd2_(ull a, ull b) {
    ull d; asm("add.rn.f32x2 %0, %1, %2;" : "=l"(d) : "l"(a), "l"(b)); return d;
}
__device__ __forceinline__ ull dup2(float x) {
    ull d; asm("mov.b64 %0, {%1, %1};" : "=l"(d) : "f"(x)); return d;
}
__device__ __forceinline__ ull pk2(float lo, float hi) {
    ull d; asm("mov.b64 %0, {%1, %2};" : "=l"(d) : "f"(lo), "f"(hi)); return d;
}
__device__ __forceinline__ void unpk(ull a, float& x, float& y) {
    asm("mov.b64 {%0, %1}, %2;" : "=f"(x), "=f"(y) : "l"(a));
}
__device__ __forceinline__ float hsum2(ull a) {
    float x, y; unpk(a, x, y); return x + y;
}
__device__ __forceinline__ float sigf(float x)   { return __fdividef(1.f, 1.f + __expf(-x)); }
__device__ __forceinline__ float tanhf_(float x) { return 1.f - __fdividef(2.f, __expf(2.f * x) + 1.f); }
__device__ __forceinline__ float leaky(float x)  { return x > 0.f ? x : 0.01f * x; }

// dot(a_pairs[NP], wrow[2*NP]) with packed FMAs; NP must be even.
template <int NP>
__device__ __forceinline__ float dotp(const ull* a, const float* wrow) {
    const ulonglong2* w = (const ulonglong2*)wrow;
    ull a0 = 0ull, a1 = 0ull;
#pragma unroll
    for (int q = 0; q < NP / 2; q++) {
        ulonglong2 ww = w[q];
        a0 = ffma2(ww.x, a[2 * q], a0);
        a1 = ffma2(ww.y, a[2 * q + 1], a1);
    }
    return hsum2(fadd2_(a0, a1));
}

// one LSTM gate pre-activation: wih_row(16) . e  +  whh_row(32) . h  + bias
__device__ __forceinline__ float gate48(const float* wih_row, const float* whh_row,
                                        const ull* e2, const ull* h2, float bias) {
    const ulonglong2* wa = (const ulonglong2*)wih_row;
    const ulonglong2* wb = (const ulonglong2*)whh_row;
    ull a0 = 0ull, a1 = 0ull;
#pragma unroll
    for (int q = 0; q < 4; q++) {
        ulonglong2 w = wa[q];
        a0 = ffma2(w.x, e2[2 * q], a0);
        a1 = ffma2(w.y, e2[2 * q + 1], a1);
    }
#pragma unroll
    for (int q = 0; q < 8; q++) {
        ulonglong2 w = wb[q];
        a0 = ffma2(w.x, h2[2 * q], a0);
        a1 = ffma2(w.y, h2[2 * q + 1], a1);
    }
    return hsum2(fadd2_(a0, a1)) + bias;
}

// x(2) -> emb(16), weights stored column-major (wc[0..15]=col0, wc[16..31]=col1)
__device__ __forceinline__ void emb16(const float* wc, const float* bb, float x, float y, ull* e2) {
    ull dx = dup2(x), dy = dup2(y);
    const ulonglong2* w0 = (const ulonglong2*)wc;
    const ulonglong2* w1 = (const ulonglong2*)(wc + 16);
    const ulonglong2* b2 = (const ulonglong2*)bb;
#pragma unroll
    for (int q = 0; q < 4; q++) {
        ulonglong2 a = w0[q], b = w1[q], c = b2[q];
        e2[2 * q]     = ffma2(a.x, dx, ffma2(b.x, dy, c.x));
        e2[2 * q + 1] = ffma2(a.y, dx, ffma2(b.y, dy, c.y));
    }
}

// One LSTM step. h2: packed old h (updated in place at the end).
// hst/cst: per-lane SMEM stash columns (stride 32 floats per state index).
__device__ __forceinline__ void lstm_step(const float* wih, const float* whh, const float* bias,
                                          const ull* e2, ull* h2, float* hst, float* cst) {
#pragma unroll 1
    for (int k = 0; k < 32; k++) {
        float gi = gate48(wih + (size_t)k * EMBD,        whh + (size_t)k * HDIM,        e2, h2, bias[k]);
        float gf = gate48(wih + (size_t)(k + 32) * EMBD, whh + (size_t)(k + 32) * HDIM, e2, h2, bias[k + 32]);
        float gg = gate48(wih + (size_t)(k + 64) * EMBD, whh + (size_t)(k + 64) * HDIM, e2, h2, bias[k + 64]);
        float go = gate48(wih + (size_t)(k + 96) * EMBD, whh + (size_t)(k + 96) * HDIM, e2, h2, bias[k + 96]);
        float ck = cst[k * 32];
        ck = sigf(gf) * ck + sigf(gi) * tanhf_(gg);
        cst[k * 32] = ck;
        hst[k * 32] = sigf(go) * tanhf_(ck);
    }
#pragma unroll
    for (int j = 0; j < 16; j++)
        h2[j] = pk2(hst[(2 * j) * 32], hst[(2 * j + 1) * 32]);
}

struct SM {
    float enc_wih[128 * 16];
    float enc_whh[128 * 32];
    float dec_wih[128 * 16];
    float dec_whh[128 * 32];
    float wq[32 * 32];
    float wk[32 * 32];
    float wv[32 * 32];
    float woT[32 * 32];     // transposed: woT[i][j] = wo[j][i]
    float mlp1[64 * 64];
    float mlp2[24 * 64];
    float enc_b[128];       // bih + bhh
    float dec_b[128];
    float eew[32];          // enc emb weights col-major
    float eeb[16];
    float dew[32];
    float deb[16];
    float lneg[32];
    float lneb[32];
    float lncg[64];
    float lncb[64];
    float m1b[64];
    float m2b[28];          // 24 used, padded
    float dow[64];          // dec_out_w rows (2 x 32)
    float dob[4];           // 2 used
    float noi[8];
    float uni[WARPS * 2048];  // per-warp 8KB: LSTM h/c stash, reused as attn K/V
};

struct Params {
    const float* obs_rel;
    const int*   se;
    const float* noise_z;
    const float* eew; const float* eeb;
    const float* e_wih; const float* e_whh; const float* e_bih; const float* e_bhh;
    const float* lneg; const float* lneb;
    const float* wq; const float* wk; const float* wv; const float* wo;
    const float* lncg; const float* lncb;
    const float* m1w; const float* m1b;
    const float* m2w; const float* m2b;
    const float* dew; const float* deb;
    const float* d_wih; const float* d_whh; const float* d_bih; const float* d_bhh;
    const float* dow; const float* dob;
    float* out;
    int n;
    int nscene;
};

__device__ __forceinline__ void cpN(float* dst, const float* src, int n, int tid) {
    for (int i = tid; i < n; i += TPB) dst[i] = src[i];
}

__global__ void __launch_bounds__(TPB)
traj_kernel(Params p) {
    extern __shared__ float smem_raw[];
    SM* s = (SM*)smem_raw;
    const int tid = threadIdx.x, warp = tid >> 5, lane = tid & 31;

    // ---- stage weights in shared ----
    cpN(s->enc_wih, p.e_wih, 2048, tid);
    cpN(s->enc_whh, p.e_whh, 4096, tid);
    cpN(s->dec_wih, p.d_wih, 2048, tid);
    cpN(s->dec_whh, p.d_whh, 4096, tid);
    cpN(s->wq, p.wq, 1024, tid);
    cpN(s->wk, p.wk, 1024, tid);
    cpN(s->wv, p.wv, 1024, tid);
    for (int i = tid; i < 1024; i += TPB) {   // transpose wo
        int r = i >> 5, c = i & 31;
        s->woT[i] = p.wo[c * 32 + r];
    }
    cpN(s->mlp1, p.m1w, 4096, tid);
    cpN(s->mlp2, p.m2w, 1536, tid);
    for (int i = tid; i < 128; i += TPB) { s->enc_b[i] = p.e_bih[i] + p.e_bhh[i]; }
    for (int i = tid; i < 128; i += TPB) { s->dec_b[i] = p.d_bih[i] + p.d_bhh[i]; }
    for (int i = tid; i < 32; i += TPB) {  // emb weights column-major
        int c = i >> 4, j = i & 15;
        s->eew[i] = p.eew[j * 2 + c];
        s->dew[i] = p.dew[j * 2 + c];
    }
    cpN(s->eeb, p.eeb, 16, tid);
    cpN(s->deb, p.deb, 16, tid);
    cpN(s->lneg, p.lneg, 32, tid);
    cpN(s->lneb, p.lneb, 32, tid);
    cpN(s->lncg, p.lncg, 64, tid);
    cpN(s->lncb, p.lncb, 64, tid);
    cpN(s->m1b, p.m1b, 64, tid);
    cpN(s->m2b, p.m2b, 24, tid);
    cpN(s->dow, p.dow, 64, tid);
    cpN(s->dob, p.dob, 2, tid);
    cpN(s->noi, p.noise_z, 8, tid);
    __syncthreads();

    const int scene = blockIdx.x * WARPS + warp;
    if (scene >= p.nscene) return;
    const int base  = p.se[2 * scene];
    const int agent = base + lane;

    float* hst = s->uni + warp * 2048 + lane;          // [k*32 + lane]
    float* cst = s->uni + warp * 2048 + 1024 + lane;

    // ---- encoder LSTM ----
#pragma unroll
    for (int k = 0; k < 32; k++) cst[k * 32] = 0.f;
    ull h2[16];
#pragma unroll
    for (int j = 0; j < 16; j++) h2[j] = 0ull;

    float lx = 0.f, ly = 0.f;
#pragma unroll 1
    for (int t = 0; t < OBS; t++) {
        float2 xy = *(const float2*)(p.obs_rel + ((size_t)t * p.n + agent) * 2);
        ull e2[8];
        emb16(s->eew, s->eeb, xy.x, xy.y, e2);
        lstm_step(s->enc_wih, s->enc_whh, s->enc_b, e2, h2, hst, cst);
        lx = xy.x; ly = xy.y;
    }

    // ---- layernorm h_enc ----
    float m = 0.f;
#pragma unroll
    for (int j = 0; j < 16; j++) m += hsum2(h2[j]);
    m *= (1.f / 32.f);
    float hl[32];
    float var = 0.f;
#pragma unroll
    for (int j = 0; j < 16; j++) {
        float a, b; unpk(h2[j], a, b);
        a -= m; b -= m;
        var += a * a + b * b;
        hl[2 * j] = a; hl[2 * j + 1] = b;
    }
    var *= (1.f / 32.f);
    float inv = rsqrtf(var + 1e-5f);
    ull ln2[16];
#pragma unroll
    for (int j = 0; j < 16; j++)
        ln2[j] = pk2(hl[2 * j] * inv * s->lneg[2 * j] + s->lneb[2 * j],
                     hl[2 * j + 1] * inv * s->lneg[2 * j + 1] + s->lneb[2 * j + 1]);

    // ---- per-scene self-attention (scene == warp) ----
    float* kb = s->uni + warp * 2048;         // reuse stash as K buffer
    float* vb = kb + 1024;                    // V buffer
    __syncwarp();
#pragma unroll
    for (int i = 0; i < 32; i++)
        kb[lane * 32 + (i ^ lane)] = dotp<16>(ln2, s->wk + i * 32);
#pragma unroll
    for (int i = 0; i < 32; i++)
        vb[lane * 32 + (i ^ lane)] = dotp<16>(ln2, s->wv + i * 32);
    __syncwarp();

    ull o2[16];
#pragma unroll
    for (int pI = 0; pI < 16; pI++) o2[pI] = 0ull;

#pragma unroll 1
    for (int hh = 0; hh < NHEAD; hh++) {
        float qh[8];
#pragma unroll
        for (int i = 0; i < 8; i++) qh[i] = dotp<16>(ln2, s->wq + (hh * 8 + i) * 32);
        float sc[32];
        float mx = -3.4e38f;
#pragma unroll
        for (int key = 0; key < 32; key++) {
            float d = 0.f;
#pragma unroll
            for (int i = 0; i < 8; i++)
                d += qh[i] * kb[key * 32 + ((hh * 8 + i) ^ key)];
            d *= 0.3535533905932738f;
            sc[key] = d;
            mx = fmaxf(mx, d);
        }
        float ssum = 0.f;
#pragma unroll
        for (int key = 0; key < 32; key++) {
            float e = __expf(sc[key] - mx);
            sc[key] = e; ssum += e;
        }
        float sinv = __fdividef(1.f, ssum);
        float av[8];
#pragma unroll
        for (int i = 0; i < 8; i++) av[i] = 0.f;
#pragma unroll
        for (int key = 0; key < 32; key++) {
            float pw = sc[key];
#pragma unroll
            for (int i = 0; i < 8; i++)
                av[i] += pw * vb[key * 32 + ((hh * 8 + i) ^ key)];
        }
        // accumulate output projection: o[j] += av[i]*sinv * woT[hh*8+i][j]
#pragma unroll
        for (int i = 0; i < 8; i++) {
            ull ad = dup2(av[i] * sinv);
            const ulonglong2* wt = (const ulonglong2*)(s->woT + (hh * 8 + i) * 32);
#pragma unroll
            for (int q = 0; q < 8; q++) {
                ulonglong2 w = wt[q];
                o2[2 * q]     = ffma2(w.x, ad, o2[2 * q]);
                o2[2 * q + 1] = ffma2(w.y, ad, o2[2 * q + 1]);
            }
        }
    }

    // ---- context layernorm over concat(h_enc_ln, attn) (64 dims) ----
    float m2 = 0.f;
#pragma unroll
    for (int j = 0; j < 16; j++) m2 += hsum2(ln2[j]);
#pragma unroll
    for (int j = 0; j < 16; j++) m2 += hsum2(o2[j]);
    m2 *= (1.f / 64.f);
    float cv[64];
    float v2 = 0.f;
#pragma unroll
    for (int j = 0; j < 16; j++) {
        float a, b; unpk(ln2[j], a, b);
        a -= m2; b -= m2; v2 += a * a + b * b;
        cv[2 * j] = a; cv[2 * j + 1] = b;
    }
#pragma unroll
    for (int j = 0; j < 16; j++) {
        float a, b; unpk(o2[j], a, b);
        a -= m2; b -= m2; v2 += a * a + b * b;
        cv[32 + 2 * j] = a; cv[33 + 2 * j] = b;
    }
    v2 *= (1.f / 64.f);
    float inv2 = rsqrtf(v2 + 1e-5f);
    ull ctx2[32];
#pragma unroll
    for (int q = 0; q < 32; q++)
        ctx2[q] = pk2(cv[2 * q] * inv2 * s->lncg[2 * q] + s->lncb[2 * q],
                      cv[2 * q + 1] * inv2 * s->lncg[2 * q + 1] + s->lncb[2 * q + 1]);

    // ---- MLP: 64 -> 64 (leaky) -> 24 (leaky), + noise -> decoder h ----
    ull x12[32];
#pragma unroll
    for (int q = 0; q < 32; q++) {
        float y0 = leaky(dotp<32>(ctx2, s->mlp1 + (2 * q) * 64) + s->m1b[2 * q]);
        float y1 = leaky(dotp<32>(ctx2, s->mlp1 + (2 * q + 1) * 64) + s->m1b[2 * q + 1]);
        x12[q] = pk2(y0, y1);
    }
    ull dh2[16];
#pragma unroll
    for (int q = 0; q < 12; q++) {
        float y0 = leaky(dotp<32>(x12, s->mlp2 + (2 * q) * 64) + s->m2b[2 * q]);
        float y1 = leaky(dotp<32>(x12, s->mlp2 + (2 * q + 1) * 64) + s->m2b[2 * q + 1]);
        dh2[q] = pk2(y0, y1);
    }
#pragma unroll
    for (int q = 0; q < 4; q++)
        dh2[12 + q] = pk2(s->noi[2 * q], s->noi[2 * q + 1]);

    // ---- decoder LSTM rollout ----
    __syncwarp();
#pragma unroll
    for (int k = 0; k < 32; k++) cst[k * 32] = 0.f;

    float rx = lx, ry = ly;
#pragma unroll 1
    for (int t = 0; t < PRED; t++) {
        ull e2[8];
        emb16(s->dew, s->deb, rx, ry, e2);
        lstm_step(s->dec_wih, s->dec_whh, s->dec_b, e2, dh2, hst, cst);
        float r0 = dotp<16>(dh2, s->dow) + s->dob[0];
        float r1 = dotp<16>(dh2, s->dow + 32) + s->dob[1];
        *(float2*)(p.out + ((size_t)t * p.n + agent) * 2) = make_float2(r0, r1);
        rx = r0; ry = r1;
    }
}

extern "C" void kernel_launch(void* const* d_in, const int* in_sizes, int n_in,
                              void* d_out, int out_size) {
    Params p;
    p.obs_rel = (const float*)d_in[1];
    p.se      = (const int*)d_in[2];
    p.noise_z = (const float*)d_in[3];
    p.eew = (const float*)d_in[4];   p.eeb = (const float*)d_in[5];
    p.e_wih = (const float*)d_in[6]; p.e_whh = (const float*)d_in[7];
    p.e_bih = (const float*)d_in[8]; p.e_bhh = (const float*)d_in[9];
    p.lneg = (const float*)d_in[10]; p.lneb = (const float*)d_in[11];
    p.wq = (const float*)d_in[12];   p.wk = (const float*)d_in[13];
    p.wv = (const float*)d_in[14];   p.wo = (const float*)d_in[15];
    p.lncg = (const float*)d_in[16]; p.lncb = (const float*)d_in[17];
    p.m1w = (const float*)d_in[18];  p.m1b = (const float*)d_in[19];
    p.m2w = (const float*)d_in[20];  p.m2b = (const float*)d_in[21];
    p.dew = (const float*)d_in[22];  p.deb = (const float*)d_in[23];
    p.d_wih = (const float*)d_in[24]; p.d_whh = (const float*)d_in[25];
    p.d_bih = (const float*)d_in[26]; p.d_bhh = (const float*)d_in[27];
    p.dow = (const float*)d_in[28];  p.dob = (const float*)d_in[29];
    p.out = (float*)d_out;
    p.n = in_sizes[1] / (OBS * 2);
    p.nscene = in_sizes[2] / 2;

    size_t smem = sizeof(SM);
    cudaFuncSetAttribute(traj_kernel, cudaFuncAttributeMaxDynamicSharedMemorySize, (int)smem);
    int grid = (p.nscene + WARPS - 1) / WARPS;
    traj_kernel<<<grid, TPB, smem>>>(p);
}

// round 4
// speedup vs baseline: 1.5586x; 1.5586x over previous
#include <cuda_runtime.h>

// TrajectoryGenerator fused kernel for GB300 (sm_103a), round 2.
// One warp == 2 scenes (agent pair per lane). Weight LDS amortized over 2
// agents; input-embedding folded into gate weights (rank-2 collapse):
//   gates = Whh@h + (Wih@A)@[x,y] + (Wih@b_e + bih + bhh)
// All inner products use packed fma.rn.f32x2.

#define OBS   20
#define PRED  30
#define WARPS 8
#define TPB   256          // 8 warps, 16 scenes per block

typedef unsigned long long ull;

__device__ __forceinline__ ull ffma2(ull a, ull b, ull c) {
    ull d; asm("fma.rn.f32x2 %0, %1, %2, %3;" : "=l"(d) : "l"(a), "l"(b), "l"(c)); return d;
}
__device__ __forceinline__ ull fadd2_(ull a, ull b) {
    ull d; asm("add.rn.f32x2 %0, %1, %2;" : "=l"(d) : "l"(a), "l"(b)); return d;
}
__device__ __forceinline__ ull dup2(float x) {
    ull d; asm("mov.b64 %0, {%1, %1};" : "=l"(d) : "f"(x)); return d;
}
__device__ __forceinline__ ull pk2(float lo, float hi) {
    ull d; asm("mov.b64 %0, {%1, %2};" : "=l"(d) : "f"(lo), "f"(hi)); return d;
}
__device__ __forceinline__ void unpk(ull a, float& x, float& y) {
    asm("mov.b64 {%0, %1}, %2;" : "=f"(x), "=f"(y) : "l"(a));
}
__device__ __forceinline__ float hsum2(ull a) {
    float x, y; unpk(a, x, y); return x + y;
}
__device__ __forceinline__ float sigf(float x)   { return __fdividef(1.f, 1.f + __expf(-x)); }
__device__ __forceinline__ float tanhf_(float x) { return 1.f - __fdividef(2.f, __expf(2.f * x) + 1.f); }
__device__ __forceinline__ float leaky(float x)  { return x > 0.f ? x : 0.01f * x; }

template <int NP>
__device__ __forceinline__ float dotp(const ull* a, const float* wrow) {
    const ulonglong2* w = (const ulonglong2*)wrow;
    ull a0 = 0ull, a1 = 0ull;
#pragma unroll
    for (int q = 0; q < NP / 2; q++) {
        ulonglong2 ww = w[q];
        a0 = ffma2(ww.x, a[2 * q], a0);
        a1 = ffma2(ww.y, a[2 * q + 1], a1);
    }
    return hsum2(fadd2_(a0, a1));
}

struct SM {
    float  enc_whh[4096];
    float  dec_whh[4096];
    float  wq[1024], wk[1024], wv[1024], woT[1024];
    float  mlp1[4096];
    float  mlp2[1536];
    float4 gw_enc[128];   // (w2x, w2y, combined_bias, 0) per gate row
    float4 gw_dec[128];
    float  lneg[32], lneb[32], lncg[64], lncb[64];
    float  m1b[64], m2b[24], dow[64], dob[2], noi[8];
    float  stash[WARPS * 4096];   // 16KB/warp: cA | cB | hpA | hpB (1024 f each)
};

struct Params {
    const float* obs_rel;
    const int*   se;
    const float* noise_z;
    const float* eew; const float* eeb;
    const float* e_wih; const float* e_whh; const float* e_bih; const float* e_bhh;
    const float* lneg; const float* lneb;
    const float* wq; const float* wk; const float* wv; const float* wo;
    const float* lncg; const float* lncb;
    const float* m1w; const float* m1b;
    const float* m2w; const float* m2b;
    const float* dew; const float* deb;
    const float* d_wih; const float* d_whh; const float* d_bih; const float* d_bhh;
    const float* dow; const float* dob;
    float* out;
    int n;
    int nscene;
};

__device__ __forceinline__ void cpN(float* dst, const float* src, int n, int tid) {
    for (int i = tid; i < n; i += TPB) dst[i] = src[i];
}

// Double LSTM step: two agents (A,B) in each lane sharing one pass over whh.
// hA/hB: packed h pairs (16 ull). cA/cB: smem c state [k*32]. hpA/hpB: smem
// ull staging [j*32] for the repack.
__device__ __forceinline__ void lstm_step2(const float* whh, const float4* gw,
                                           float xA, float yA, float xB, float yB,
                                           ull* hA, ull* hB,
                                           float* cA, float* cB,
                                           ull* hpA, ull* hpB) {
#pragma unroll 1
    for (int j = 0; j < 16; j++) {
        float hnA[2], hnB[2];
#pragma unroll
        for (int half = 0; half < 2; half++) {
            const int k = 2 * j + half;
            float gA[4], gB[4];
#pragma unroll
            for (int g = 0; g < 4; g++) {
                const int row = g * 32 + k;
                const ulonglong2* w = (const ulonglong2*)(whh + row * 32);
                float4 gv = gw[row];
                ull a0 = 0ull, a1 = 0ull, b0 = 0ull, b1 = 0ull;
#pragma unroll
                for (int q = 0; q < 8; q++) {
                    ulonglong2 ww = w[q];
                    a0 = ffma2(ww.x, hA[2 * q], a0);
                    a1 = ffma2(ww.y, hA[2 * q + 1], a1);
                    b0 = ffma2(ww.x, hB[2 * q], b0);
                    b1 = ffma2(ww.y, hB[2 * q + 1], b1);
                }
                gA[g] = fmaf(gv.x, xA, fmaf(gv.y, yA, gv.z + hsum2(fadd2_(a0, a1))));
                gB[g] = fmaf(gv.x, xB, fmaf(gv.y, yB, gv.z + hsum2(fadd2_(b0, b1))));
            }
            {
                float c = cA[k * 32];
                c = sigf(gA[1]) * c + sigf(gA[0]) * tanhf_(gA[2]);
                cA[k * 32] = c;
                hnA[half] = sigf(gA[3]) * tanhf_(c);
            }
            {
                float c = cB[k * 32];
                c = sigf(gB[1]) * c + sigf(gB[0]) * tanhf_(gB[2]);
                cB[k * 32] = c;
                hnB[half] = sigf(gB[3]) * tanhf_(c);
            }
        }
        hpA[j * 32] = pk2(hnA[0], hnA[1]);
        hpB[j * 32] = pk2(hnB[0], hnB[1]);
    }
#pragma unroll
    for (int j = 0; j < 16; j++) { hA[j] = hpA[j * 32]; hB[j] = hpB[j * 32]; }
}

// layernorm 32 dims (packed) -> packed output
__device__ __forceinline__ void ln32(const ull* h, const float* gg, const float* bb, ull* o) {
    float m = 0.f;
#pragma unroll
    for (int j = 0; j < 16; j++) m += hsum2(h[j]);
    m *= (1.f / 32.f);
    float var = 0.f;
    float hl[32];
#pragma unroll
    for (int j = 0; j < 16; j++) {
        float a, b; unpk(h[j], a, b);
        a -= m; b -= m;
        var += a * a + b * b;
        hl[2 * j] = a; hl[2 * j + 1] = b;
    }
    var *= (1.f / 32.f);
    float inv = rsqrtf(var + 1e-5f);
#pragma unroll
    for (int j = 0; j < 16; j++)
        o[j] = pk2(hl[2 * j] * inv * gg[2 * j] + bb[2 * j],
                   hl[2 * j + 1] * inv * gg[2 * j + 1] + bb[2 * j + 1]);
}

// per-scene attention + ctx-LN + MLP; ln2: LN'd encoder state of this lane's
// agent for this scene. kb/vb: 1024-float scene buffers. Result: dh2 (16 ull).
__device__ __forceinline__ void attn_mlp(const SM* s, const ull* ln2,
                                         float* kb, float* vb, int lane, ull* dh2) {
    __syncwarp();
#pragma unroll
    for (int i = 0; i < 32; i++)
        kb[lane * 32 + (i ^ lane)] = dotp<16>(ln2, s->wk + i * 32);
#pragma unroll
    for (int i = 0; i < 32; i++)
        vb[lane * 32 + (i ^ lane)] = dotp<16>(ln2, s->wv + i * 32);
    __syncwarp();

    ull o2[16];
#pragma unroll
    for (int q = 0; q < 16; q++) o2[q] = 0ull;

#pragma unroll 1
    for (int hh = 0; hh < 4; hh++) {
        float qh[8];
#pragma unroll
        for (int i = 0; i < 8; i++) qh[i] = dotp<16>(ln2, s->wq + (hh * 8 + i) * 32);
        float sc[32];
        float mx = -3.4e38f;
#pragma unroll
        for (int key = 0; key < 32; key++) {
            float d = 0.f;
#pragma unroll
            for (int i = 0; i < 8; i++)
                d += qh[i] * kb[key * 32 + ((hh * 8 + i) ^ key)];
            d *= 0.3535533905932738f;
            sc[key] = d;
            mx = fmaxf(mx, d);
        }
        float ssum = 0.f;
#pragma unroll
        for (int key = 0; key < 32; key++) {
            float e = __expf(sc[key] - mx);
            sc[key] = e; ssum += e;
        }
        float sinv = __fdividef(1.f, ssum);
        float av[8];
#pragma unroll
        for (int i = 0; i < 8; i++) av[i] = 0.f;
#pragma unroll
        for (int key = 0; key < 32; key++) {
            float pw = sc[key];
#pragma unroll
            for (int i = 0; i < 8; i++)
                av[i] += pw * vb[key * 32 + ((hh * 8 + i) ^ key)];
        }
#pragma unroll
        for (int i = 0; i < 8; i++) {
            ull ad = dup2(av[i] * sinv);
            const ulonglong2* wt = (const ulonglong2*)(s->woT + (hh * 8 + i) * 32);
#pragma unroll
            for (int q = 0; q < 8; q++) {
                ulonglong2 w = wt[q];
                o2[2 * q]     = ffma2(w.x, ad, o2[2 * q]);
                o2[2 * q + 1] = ffma2(w.y, ad, o2[2 * q + 1]);
            }
        }
    }

    // ctx layernorm over concat(ln2, o2) (64 dims)
    float m2 = 0.f;
#pragma unroll
    for (int j = 0; j < 16; j++) m2 += hsum2(ln2[j]) + hsum2(o2[j]);
    m2 *= (1.f / 64.f);
    float cv[64];
    float v2 = 0.f;
#pragma unroll
    for (int j = 0; j < 16; j++) {
        float a, b; unpk(ln2[j], a, b);
        a -= m2; b -= m2; v2 += a * a + b * b;
        cv[2 * j] = a; cv[2 * j + 1] = b;
    }
#pragma unroll
    for (int j = 0; j < 16; j++) {
        float a, b; unpk(o2[j], a, b);
        a -= m2; b -= m2; v2 += a * a + b * b;
        cv[32 + 2 * j] = a; cv[33 + 2 * j] = b;
    }
    v2 *= (1.f / 64.f);
    float inv2 = rsqrtf(v2 + 1e-5f);
    ull ctx2[32];
#pragma unroll
    for (int q = 0; q < 32; q++)
        ctx2[q] = pk2(cv[2 * q] * inv2 * s->lncg[2 * q] + s->lncb[2 * q],
                      cv[2 * q + 1] * inv2 * s->lncg[2 * q + 1] + s->lncb[2 * q + 1]);

    ull x12[32];
#pragma unroll
    for (int q = 0; q < 32; q++) {
        float y0 = leaky(dotp<32>(ctx2, s->mlp1 + (2 * q) * 64) + s->m1b[2 * q]);
        float y1 = leaky(dotp<32>(ctx2, s->mlp1 + (2 * q + 1) * 64) + s->m1b[2 * q + 1]);
        x12[q] = pk2(y0, y1);
    }
#pragma unroll
    for (int q = 0; q < 12; q++) {
        float y0 = leaky(dotp<32>(x12, s->mlp2 + (2 * q) * 64) + s->m2b[2 * q]);
        float y1 = leaky(dotp<32>(x12, s->mlp2 + (2 * q + 1) * 64) + s->m2b[2 * q + 1]);
        dh2[q] = pk2(y0, y1);
    }
#pragma unroll
    for (int q = 0; q < 4; q++)
        dh2[12 + q] = pk2(s->noi[2 * q], s->noi[2 * q + 1]);
}

__global__ void __launch_bounds__(TPB)
traj_kernel(Params p) {
    extern __shared__ float smem_raw[];
    SM* s = (SM*)smem_raw;
    const int tid = threadIdx.x, warp = tid >> 5, lane = tid & 31;

    // ---- stage weights ----
    cpN(s->enc_whh, p.e_whh, 4096, tid);
    cpN(s->dec_whh, p.d_whh, 4096, tid);
    cpN(s->wq, p.wq, 1024, tid);
    cpN(s->wk, p.wk, 1024, tid);
    cpN(s->wv, p.wv, 1024, tid);
    for (int i = tid; i < 1024; i += TPB) {
        int r = i >> 5, c = i & 31;
        s->woT[i] = p.wo[c * 32 + r];
    }
    cpN(s->mlp1, p.m1w, 4096, tid);
    cpN(s->mlp2, p.m2w, 1536, tid);
    // rank-2 collapsed input weights + combined bias (one row per thread)
    {
        int row = tid & 127;
        const float* wih   = (tid < 128) ? p.e_wih : p.d_wih;
        const float* emw   = (tid < 128) ? p.eew   : p.dew;
        const float* emb_b = (tid < 128) ? p.eeb   : p.deb;
        const float* bih   = (tid < 128) ? p.e_bih : p.d_bih;
        const float* bhh   = (tid < 128) ? p.e_bhh : p.d_bhh;
        float wx = 0.f, wy = 0.f, cb = 0.f;
#pragma unroll
        for (int j = 0; j < 16; j++) {
            float w = wih[row * 16 + j];
            wx += w * emw[j * 2 + 0];
            wy += w * emw[j * 2 + 1];
            cb += w * emb_b[j];
        }
        cb += bih[row] + bhh[row];
        float4 v = make_float4(wx, wy, cb, 0.f);
        if (tid < 128) s->gw_enc[row] = v; else s->gw_dec[row] = v;
    }
    cpN(s->lneg, p.lneg, 32, tid);
    cpN(s->lneb, p.lneb, 32, tid);
    cpN(s->lncg, p.lncg, 64, tid);
    cpN(s->lncb, p.lncb, 64, tid);
    cpN(s->m1b, p.m1b, 64, tid);
    cpN(s->m2b, p.m2b, 24, tid);
    cpN(s->dow, p.dow, 64, tid);
    cpN(s->dob, p.dob, 2, tid);
    cpN(s->noi, p.noise_z, 8, tid);
    __syncthreads();

    const int sceneA = (blockIdx.x * WARPS + warp) * 2;
    if (sceneA >= p.nscene) return;
    const int sceneB = sceneA + 1;
    const bool hasB = (sceneB < p.nscene);
    const int baseA = p.se[2 * sceneA];
    const int baseB = hasB ? p.se[2 * sceneB] : baseA;
    const int agA = baseA + lane;
    const int agB = baseB + lane;

    float* wst = s->stash + warp * 4096;
    float* cA = wst + lane;                       // [k*32]
    float* cB = wst + 1024 + lane;
    ull*  hpA = (ull*)(wst + 2048) + lane;        // [j*32]
    ull*  hpB = (ull*)(wst + 3072) + lane;

    // ---- encoder ----
#pragma unroll
    for (int k = 0; k < 32; k++) { cA[k * 32] = 0.f; cB[k * 32] = 0.f; }
    ull hA[16], hB[16];
#pragma unroll
    for (int j = 0; j < 16; j++) { hA[j] = 0ull; hB[j] = 0ull; }

    float lxA = 0.f, lyA = 0.f, lxB = 0.f, lyB = 0.f;
#pragma unroll 1
    for (int t = 0; t < OBS; t++) {
        float2 a = *(const float2*)(p.obs_rel + ((size_t)t * p.n + agA) * 2);
        float2 b = *(const float2*)(p.obs_rel + ((size_t)t * p.n + agB) * 2);
        lstm_step2(s->enc_whh, s->gw_enc, a.x, a.y, b.x, b.y, hA, hB, cA, cB, hpA, hpB);
        lxA = a.x; lyA = a.y; lxB = b.x; lyB = b.y;
    }

    // ---- LN of both agents ----
    ull lnA[16], lnB[16];
    ln32(hA, s->lneg, s->lneb, lnA);
    ln32(hB, s->lneg, s->lneb, lnB);

    // ---- attention + MLP, scene A then scene B (kb/vb reuse c region) ----
    float* kb = wst;          // c state dead until decoder re-init
    float* vb = wst + 1024;
    ull dhA[16], dhB[16];
    attn_mlp(s, lnA, kb, vb, lane, dhA);
    // park dhA in hp region while doing scene B
#pragma unroll
    for (int j = 0; j < 16; j++) hpA[j * 32] = dhA[j];
    attn_mlp(s, lnB, kb, vb, lane, dhB);
#pragma unroll
    for (int j = 0; j < 16; j++) dhA[j] = hpA[j * 32];

    // ---- decoder ----
    __syncwarp();
#pragma unroll
    for (int k = 0; k < 32; k++) { cA[k * 32] = 0.f; cB[k * 32] = 0.f; }

    float rxA = lxA, ryA = lyA, rxB = lxB, ryB = lyB;
#pragma unroll 1
    for (int t = 0; t < PRED; t++) {
        lstm_step2(s->dec_whh, s->gw_dec, rxA, ryA, rxB, ryB, dhA, dhB, cA, cB, hpA, hpB);
        float a0 = dotp<16>(dhA, s->dow) + s->dob[0];
        float a1 = dotp<16>(dhA, s->dow + 32) + s->dob[1];
        float b0 = dotp<16>(dhB, s->dow) + s->dob[0];
        float b1 = dotp<16>(dhB, s->dow + 32) + s->dob[1];
        *(float2*)(p.out + ((size_t)t * p.n + agA) * 2) = make_float2(a0, a1);
        if (hasB)
            *(float2*)(p.out + ((size_t)t * p.n + agB) * 2) = make_float2(b0, b1);
        rxA = a0; ryA = a1; rxB = b0; ryB = b1;
    }
}

extern "C" void kernel_launch(void* const* d_in, const int* in_sizes, int n_in,
                              void* d_out, int out_size) {
    Params p;
    p.obs_rel = (const float*)d_in[1];
    p.se      = (const int*)d_in[2];
    p.noise_z = (const float*)d_in[3];
    p.eew = (const float*)d_in[4];   p.eeb = (const float*)d_in[5];
    p.e_wih = (const float*)d_in[6]; p.e_whh = (const float*)d_in[7];
    p.e_bih = (const float*)d_in[8]; p.e_bhh = (const float*)d_in[9];
    p.lneg = (const float*)d_in[10]; p.lneb = (const float*)d_in[11];
    p.wq = (const float*)d_in[12];   p.wk = (const float*)d_in[13];
    p.wv = (const float*)d_in[14];   p.wo = (const float*)d_in[15];
    p.lncg = (const float*)d_in[16]; p.lncb = (const float*)d_in[17];
    p.m1w = (const float*)d_in[18];  p.m1b = (const float*)d_in[19];
    p.m2w = (const float*)d_in[20];  p.m2b = (const float*)d_in[21];
    p.dew = (const float*)d_in[22];  p.deb = (const float*)d_in[23];
    p.d_wih = (const float*)d_in[24]; p.d_whh = (const float*)d_in[25];
    p.d_bih = (const float*)d_in[26]; p.d_bhh = (const float*)d_in[27];
    p.dow = (const float*)d_in[28];  p.dob = (const float*)d_in[29];
    p.out = (float*)d_out;
    p.n = in_sizes[1] / (OBS * 2);
    p.nscene = in_sizes[2] / 2;

    size_t smem = sizeof(SM);
    cudaFuncSetAttribute(traj_kernel, cudaFuncAttributeMaxDynamicSharedMemorySize, (int)smem);
    int scenesPerBlock = 2 * WARPS;
    int grid = (p.nscene + scenesPerBlock - 1) / scenesPerBlock;
    traj_kernel<<<grid, TPB, smem>>>(p);
}